// round 14
// baseline (speedup 1.0000x reference)
#include <cuda_runtime.h>
#include <cuda_fp16.h>
#include <cstdint>

#define H      128
#define NREL   237
#define NB     100
#define RTILE  16
#define MAXN   15000
#define MAXE   400000
#define EM     128        // edges per tile
#define CHUNK  512        // edges per chunk (4 tiles, tile-aligned)
#define BPH    72         // smem pitch in uint32 (half2); 72%32==8 -> conflict-free LDS.64
#define SORTB  148        // persistent blocks for fused sort
#define EGRID  296        // persistent edge CTAs (2 per SM)

// ---------------- device-global scratch (no runtime allocation) -------------
__device__ uint32_t g_Wh[2][(NREL + 1) * 8192]; // W^T fp16 per layer (slot NREL = loop_w)
__device__ uint32_t g_xh[MAXN * 64];          // x fp16, paired-k per row
__device__ float g_h1[MAXN * H];
__device__ int   g_perm[MAXE + MAXN];
__device__ int   g_counts[256];
__device__ int   g_start[256];
__device__ int   g_cursor[256];
__device__ int   g_cbase[257];                // chunk prefix per relation
__device__ unsigned g_barcnt;
__device__ unsigned g_barflag;

static const int SMEM_EDGE = 3 * 128 * BPH * 4 + 2 * 128 * 8;        // 112640

extern __shared__ char dyn_smem[];

// ---------------- PTX helpers ------------------------------------------------
__device__ __forceinline__ uint32_t h2pack(float a, float b) {
    __half2 h = __floats2half2_rn(a, b);   // a -> low, b -> high
    return *(uint32_t*)&h;
}
__device__ __forceinline__ void red_add_v4(float* p, float a, float b,
                                           float c, float d) {
    asm volatile("red.global.add.v4.f32 [%0], {%1,%2,%3,%4};"
                 :: "l"(p), "f"(a), "f"(b), "f"(c), "f"(d) : "memory");
}
__device__ __forceinline__ void mma_16n8k16(float* c, const uint32_t* a,
                                            uint32_t b0, uint32_t b1) {
    asm volatile(
        "mma.sync.aligned.m16n8k16.row.col.f32.f16.f16.f32 "
        "{%0,%1,%2,%3}, {%4,%5,%6,%7}, {%8,%9}, {%0,%1,%2,%3};"
        : "+f"(c[0]), "+f"(c[1]), "+f"(c[2]), "+f"(c[3])
        : "r"(a[0]), "r"(a[1]), "r"(a[2]), "r"(a[3]), "r"(b0), "r"(b1));
}
__device__ __forceinline__ void cpa16(void* s, const void* g) {
    uint32_t sa = (uint32_t)__cvta_generic_to_shared(s);
    asm volatile("cp.async.cg.shared.global [%0], [%1], 16;"
                 :: "r"(sa), "l"(g) : "memory");
}
__device__ __forceinline__ void cpa16z(void* s, const void* g) {
    uint32_t sa = (uint32_t)__cvta_generic_to_shared(s);
    asm volatile("cp.async.cg.shared.global [%0], [%1], 16, 0;"
                 :: "r"(sa), "l"(g) : "memory");
}
#define CPA_COMMIT() asm volatile("cp.async.commit_group;" ::: "memory")
#define CPA_WAIT1()  asm volatile("cp.async.wait_group 1;" ::: "memory")
#define CPA_WAIT0()  asm volatile("cp.async.wait_group 0;" ::: "memory")

// pack 16 consecutive floats (4 float4) into paired-k half2 order
__device__ __forceinline__ void pack_kgroup(const float4* u, uint4* o0, uint4* o1) {
    uint32_t q0 = h2pack(u[0].x, u[0].y), q1 = h2pack(u[0].z, u[0].w);
    uint32_t q2 = h2pack(u[1].x, u[1].y), q3 = h2pack(u[1].z, u[1].w);
    uint32_t q4 = h2pack(u[2].x, u[2].y), q5 = h2pack(u[2].z, u[2].w);
    uint32_t q6 = h2pack(u[3].x, u[3].y), q7 = h2pack(u[3].z, u[3].w);
    *o0 = make_uint4(q0, q4, q1, q5);
    *o1 = make_uint4(q2, q6, q3, q7);
}

// grid-wide barrier (persistent kernel, grid <= resident capacity).
__device__ __forceinline__ void gridbar(int nb) {
    __syncthreads();
    if (threadIdx.x == 0) {
        unsigned old = *(volatile unsigned*)&g_barflag;
        __threadfence();
        unsigned t = atomicAdd(&g_barcnt, 1);
        if (t == (unsigned)nb - 1) {
            g_barcnt = 0;
            __threadfence();
            atomicAdd(&g_barflag, 1);
        } else {
            while (*(volatile unsigned*)&g_barflag == old) {}
        }
        __threadfence();
    }
    __syncthreads();
}

// ---- fused counting-sort: block-aggregated scatter, analytic self-loops ----
__global__ void __launch_bounds__(256, 1)
sort_kernel(const int* __restrict__ etype, int E, int total) {
    __shared__ int sh[256];
    __shared__ int ss[256];
    int b = blockIdx.x, nb = gridDim.x, tid = threadIdx.x;
    int nN = total - E;

    if (b == 0) g_counts[tid] = 0;
    gridbar(nb);

    sh[tid] = 0;
    __syncthreads();
    for (int e = b * 256 + tid; e < E; e += nb * 256)
        atomicAdd(&sh[etype[e]], 1);
    __syncthreads();
    if (sh[tid]) atomicAdd(&g_counts[tid], sh[tid]);
    gridbar(nb);

    if (b == 0) {
        int c = g_counts[tid] + ((tid == NREL) ? nN : 0);
        g_counts[tid] = c;
        ss[tid] = c;
        __syncthreads();
        #pragma unroll
        for (int off = 1; off < 256; off <<= 1) {
            int v = (tid >= off) ? ss[tid - off] : 0;
            __syncthreads();
            ss[tid] += v;
            __syncthreads();
        }
        g_start[tid] = ss[tid] - c;
        g_cursor[tid] = ss[tid] - c;
        __syncthreads();
        int C = (c + CHUNK - 1) / CHUNK;
        ss[tid] = C;
        __syncthreads();
        #pragma unroll
        for (int off = 1; off < 256; off <<= 1) {
            int v = (tid >= off) ? ss[tid - off] : 0;
            __syncthreads();
            ss[tid] += v;
            __syncthreads();
        }
        g_cbase[tid] = ss[tid] - C;
        if (tid == 255) g_cbase[256] = ss[255];
    }
    gridbar(nb);

    ss[tid] = (sh[tid] > 0) ? atomicAdd(&g_cursor[tid], sh[tid]) : 0;
    __syncthreads();
    for (int e = b * 256 + tid; e < E; e += nb * 256) {
        int p = atomicAdd(&ss[etype[e]], 1);
        g_perm[p] = e;
    }
    {
        int base = g_start[NREL];
        for (int i = b * 256 + tid; i < nN; i += nb * 256)
            g_perm[base + i] = E + i;
    }
}

// ---- xh gather + bias init: g_xh = fp16(emb[nids]); outinit = bias ---------
__global__ void xh_gather_kernel(const float* __restrict__ emb,
                                 const int* __restrict__ nids,
                                 const float* __restrict__ bias,
                                 float* __restrict__ outinit, int n) {
    int idx = blockIdx.x * blockDim.x + threadIdx.x;
    if (idx >= n * 8) return;
    int node = idx >> 3, kg = idx & 7;
    const float4* xr = (const float4*)emb + (size_t)nids[node] * 32 + kg * 4;
    float4 u[4] = {xr[0], xr[1], xr[2], xr[3]};
    uint4 o0, o1;
    pack_kgroup(u, &o0, &o1);
    uint4* d = (uint4*)(g_xh + (size_t)node * 64 + kg * 8);
    d[0] = o0; d[1] = o1;
    const float4* b4 = (const float4*)bias + kg * 4;
    float4* ob = (float4*)outinit + (size_t)node * 32 + kg * 4;
    #pragma unroll
    for (int i = 0; i < 4; i++) ob[i] = b4[i];
}

// ---- relu h1 -> g_xh (fp16 paired-k); out init = bias2 ---------------------
__global__ void relu_xh_kernel(const float* __restrict__ bias,
                               float* __restrict__ outinit, int n) {
    int idx = blockIdx.x * blockDim.x + threadIdx.x;
    if (idx >= n * 8) return;
    int node = idx >> 3, kg = idx & 7;
    const float4* hr = (const float4*)g_h1 + (size_t)node * 32 + kg * 4;
    float4 u[4];
    #pragma unroll
    for (int i = 0; i < 4; i++) {
        float4 v = hr[i];
        v.x = fmaxf(v.x, 0.f); v.y = fmaxf(v.y, 0.f);
        v.z = fmaxf(v.z, 0.f); v.w = fmaxf(v.w, 0.f);
        u[i] = v;
    }
    uint4 o0, o1;
    pack_kgroup(u, &o0, &o1);
    uint4* d = (uint4*)(g_xh + (size_t)node * 64 + kg * 8);
    d[0] = o0; d[1] = o1;
    const float4* b4 = (const float4*)bias + kg * 4;
    float4* ob = (float4*)outinit + (size_t)node * 32 + kg * 4;
    #pragma unroll
    for (int i = 0; i < 4; i++) ob[i] = b4[i];
}

// ---- wbuildh (both layers in one launch, z selects): fp16 W^T, permuted ----
__global__ void wbuildh_kernel(const float* __restrict__ V1,
                               const float* __restrict__ comp1,
                               const float* __restrict__ loop1,
                               const float* __restrict__ V2,
                               const float* __restrict__ comp2,
                               const float* __restrict__ loop2) {
    int layer = blockIdx.z;
    const float* V     = layer ? V2 : V1;
    const float* comp  = layer ? comp2 : comp1;
    const float* loopw = layer ? loop2 : loop1;
    uint32_t* Wout = g_Wh[layer];

    __shared__ float sC[RTILE * NB];
    int r0 = blockIdx.y * RTILE;
    for (int i = threadIdx.x; i < RTILE * NB; i += 128) {
        int rr = i / NB, b = i % NB;
        int r = r0 + rr;
        sC[i] = (r < NREL) ? comp[r * NB + b] : 0.f;
    }
    __syncthreads();
    int kp = blockIdx.x;          // k-pair 0..63
    int n = threadIdx.x;          // 0..127
    float a0[RTILE], a1[RTILE];
    #pragma unroll
    for (int rr = 0; rr < RTILE; rr++) { a0[rr] = 0.f; a1[rr] = 0.f; }
    const float* v0p = V + (size_t)(2 * kp) * 128 + n;
    #pragma unroll 2
    for (int b = 0; b < NB; b++) {
        float v0 = v0p[(size_t)b * (H * H)];
        float v1 = v0p[(size_t)b * (H * H) + 128];
        #pragma unroll
        for (int rr = 0; rr < RTILE; rr++) {
            float c = sC[rr * NB + b];
            a0[rr] += c * v0;
            a1[rr] += c * v1;
        }
    }
    int half = n >> 6, rem = n & 63;
    int qq = rem >> 4, t4 = (rem >> 2) & 3, p = (rem >> 1) & 1, bb = rem & 1;
    int srow = half * 64 + (2 * qq + p) * 8 + t4 * 2 + bb;
    int kg = kp >> 3, j0 = kp & 7;
    int pos = (j0 < 4) ? 2 * j0 : 2 * j0 - 7;
    int off = srow * 64 + kg * 8 + pos;
    #pragma unroll
    for (int rr = 0; rr < RTILE; rr++) {
        int r = r0 + rr;
        if (r < NREL) {
            Wout[(size_t)r * 8192 + off] = h2pack(a0[rr], a1[rr]);
        } else if (r == NREL) {
            float l0 = loopw[(size_t)(2 * kp) * 128 + n];
            float l1 = loopw[(size_t)(2 * kp + 1) * 128 + n];
            Wout[(size_t)NREL * 8192 + off] = h2pack(l0, l1);
        }
    }
}

// -------- persistent FP16 mma.sync edge GEMM: contiguous chunk ranges --------
// 296 CTAs, each owns chunks [c0,c1). B re-staged only when relation changes.
__global__ void __launch_bounds__(256, 2)
edge_mma_kernel(const uint32_t* __restrict__ Wh,
                const int* __restrict__ src,
                const int* __restrict__ dst,
                const float* __restrict__ norm,
                float* __restrict__ hout, int E) {
    uint32_t* sB  = (uint32_t*)dyn_smem;          // [128][BPH]
    uint32_t* sA0 = sB + 128 * BPH;               // [128][BPH] buf 0
    uint32_t* sA1 = sA0 + 128 * BPH;              // [128][BPH] buf 1
    int*   sDst = (int*)(sA1 + 128 * BPH);        // [2][128]
    float* sNrm = (float*)(sDst + 256);           // [2][128]
    uint32_t* sAbuf[2] = {sA0, sA1};

    int tid = threadIdx.x, lane = tid & 31, wid = tid >> 5;
    int g = lane >> 2, tig = lane & 3;
    int wm = wid >> 1, wn = wid & 1;              // 4 x 2 warp grid
    int m0 = wm * 32, n0 = wn * 64;

    int totalChunks = g_cbase[NREL + 1];
    int c0 = (int)(((long long)totalChunks * blockIdx.x) / EGRID);
    int c1 = (int)(((long long)totalChunks * (blockIdx.x + 1)) / EGRID);
    if (c0 >= c1) return;

    // rel of chunk c0 (binary search, uniform)
    int rel;
    {
        int loR = 0, hiR = NREL;
        while (loR < hiR) {
            int m = (loR + hiR + 1) >> 1;
            if (g_cbase[m] <= c0) loR = m; else hiR = m - 1;
        }
        rel = loR;
    }
    int c = c0;
    int tile = g_start[rel] + (c - g_cbase[rel]) * CHUNK;
    int chunkHi = min(g_start[rel] + g_counts[rel], tile + CHUNK);

    auto stageB = [&](int r) {
        const uint32_t* wb = Wh + (size_t)r * 8192;
        #pragma unroll
        for (int i = 0; i < 8; i++) {
            int ci = tid + i * 256;
            int row = ci >> 4, cc = ci & 15;
            cpa16(&sB[row * BPH + cc * 4], &wb[row * 64 + cc * 4]);
        }
    };
    int arow = tid >> 1, ahalf = tid & 1;
    auto issueA = [&](int t0, int hiT, int bsel) {
        int r = t0 + arow;
        uint32_t* sp = sAbuf[bsel] + arow * BPH + ahalf * 32;
        if (r < hiT) {
            int e = g_perm[r];
            int node;
            if (e < E) {
                node = src[e];
                if (ahalf == 0) {
                    sDst[bsel * 128 + arow] = dst[e];
                    sNrm[bsel * 128 + arow] = norm[e];
                }
            } else {
                node = e - E;    // self-loop pseudo-edge
                if (ahalf == 0) {
                    sDst[bsel * 128 + arow] = node;
                    sNrm[bsel * 128 + arow] = 1.0f;
                }
            }
            const uint32_t* gp = g_xh + (size_t)node * 64 + ahalf * 32;
            #pragma unroll
            for (int cc = 0; cc < 8; cc++) cpa16(sp + cc * 4, gp + cc * 4);
        } else {
            #pragma unroll
            for (int cc = 0; cc < 8; cc++) cpa16z(sp + cc * 4, g_xh);
        }
    };

    bool aReady = false;
    bool needB = true;
    int it = 0;

    while (tile >= 0) {
        int bsel = it & 1;
        if (!aReady) {
            if (needB) stageB(rel);
            issueA(tile, chunkHi, bsel);
            CPA_COMMIT();
        }
        // ---- compute next-tile state (uniform scalars) ----
        int nc = c, nrel = rel, ntile = tile + EM, nHi = chunkHi;
        bool nNew = false;
        if (ntile >= chunkHi) {
            nc = c + 1;
            if (nc >= c1) {
                ntile = -1;
            } else {
                while (g_cbase[nrel + 1] <= nc) { nrel++; nNew = true; }
                int nlo = g_start[nrel] + (nc - g_cbase[nrel]) * CHUNK;
                nHi = min(g_start[nrel] + g_counts[nrel], nlo + CHUNK);
                ntile = nlo;
            }
        }
        bool pref = (ntile >= 0) && !nNew;
        if (pref) {
            issueA(ntile, nHi, bsel ^ 1);
            CPA_COMMIT();
            CPA_WAIT1();        // current tile's data resident
        } else {
            CPA_WAIT0();        // flush (rel change or end)
        }
        __syncthreads();

        int tsize = min(EM, chunkHi - tile);
        uint32_t* sA = sAbuf[bsel];

        float acc[2][8][4];
        #pragma unroll
        for (int mi = 0; mi < 2; mi++)
            #pragma unroll
            for (int ni = 0; ni < 8; ni++)
                #pragma unroll
                for (int cc = 0; cc < 4; cc++) acc[mi][ni][cc] = 0.f;

        #pragma unroll
        for (int ks = 0; ks < 8; ks++) {
            int base = ks * 8 + 2 * tig;
            uint32_t a[2][4];
            #pragma unroll
            for (int mi = 0; mi < 2; mi++) {
                uint2 alo = *(const uint2*)&sA[(m0 + mi * 16 + g) * BPH + base];
                uint2 ahi = *(const uint2*)&sA[(m0 + mi * 16 + g + 8) * BPH + base];
                a[mi][0] = alo.x; a[mi][2] = alo.y;
                a[mi][1] = ahi.x; a[mi][3] = ahi.y;
            }
            #pragma unroll
            for (int ni = 0; ni < 8; ni++) {
                uint2 bb = *(const uint2*)&sB[(n0 + ni * 8 + g) * BPH + base];
                mma_16n8k16(acc[0][ni], a[0], bb.x, bb.y);
                mma_16n8k16(acc[1][ni], a[1], bb.x, bb.y);
            }
        }

        #pragma unroll
        for (int mi = 0; mi < 2; mi++) {
            int r0 = m0 + mi * 16 + g;
            int r1 = r0 + 8;
            bool v0 = r0 < tsize, v1 = r1 < tsize;
            float nr0 = sNrm[bsel * 128 + r0], nr1 = sNrm[bsel * 128 + r1];
            float* p0 = hout + (size_t)sDst[bsel * 128 + r0] * H;
            float* p1 = hout + (size_t)sDst[bsel * 128 + r1] * H;
            #pragma unroll
            for (int q = 0; q < 4; q++) {
                int cc = n0 + q * 16 + tig * 4;
                if (v0) red_add_v4(p0 + cc,
                                   acc[mi][2 * q][0] * nr0,
                                   acc[mi][2 * q][1] * nr0,
                                   acc[mi][2 * q + 1][0] * nr0,
                                   acc[mi][2 * q + 1][1] * nr0);
                if (v1) red_add_v4(p1 + cc,
                                   acc[mi][2 * q][2] * nr1,
                                   acc[mi][2 * q][3] * nr1,
                                   acc[mi][2 * q + 1][2] * nr1,
                                   acc[mi][2 * q + 1][3] * nr1);
            }
        }
        __syncthreads();   // buffer/B reuse safety

        c = nc; rel = nrel; tile = ntile; chunkHi = nHi;
        needB = nNew; aReady = pref;
        it++;
    }
}

// ---------------- host orchestration ----------------------------------------
extern "C" void kernel_launch(void* const* d_in, const int* in_sizes, int n_in,
                              void* d_out, int out_size) {
    const int*   nids  = (const int*)d_in[0];
    const int*   src   = (const int*)d_in[1];
    const int*   dst   = (const int*)d_in[2];
    const int*   etype = (const int*)d_in[3];
    const float* norm  = (const float*)d_in[4];
    const float* emb   = (const float*)d_in[6];
    const float* V1    = (const float*)d_in[7];
    const float* comp1 = (const float*)d_in[8];
    const float* loop1 = (const float*)d_in[9];
    const float* bias1 = (const float*)d_in[10];
    const float* V2    = (const float*)d_in[11];
    const float* comp2 = (const float*)d_in[12];
    const float* loop2 = (const float*)d_in[13];
    const float* bias2 = (const float*)d_in[14];
    float* out = (float*)d_out;

    int nN = in_sizes[0];
    int E  = in_sizes[1];

    cudaFuncSetAttribute(edge_mma_kernel,
                         cudaFuncAttributeMaxDynamicSharedMemorySize, SMEM_EDGE);

    float* ph1 = nullptr;
    uint32_t* pWh = nullptr;
    cudaGetSymbolAddress((void**)&ph1, g_h1);
    cudaGetSymbolAddress((void**)&pWh, g_Wh);
    uint32_t* pWh1 = pWh;
    uint32_t* pWh2 = pWh + (size_t)(NREL + 1) * 8192;

    dim3 wgrid(64, (NREL + 1 + RTILE - 1) / RTILE, 2);
    int xgrid = (nN * 8 + 255) / 256;

    sort_kernel<<<SORTB, 256>>>(etype, E, E + nN);                        // 0
    xh_gather_kernel<<<xgrid, 256>>>(emb, nids, bias1, ph1, nN);          // 1
    wbuildh_kernel<<<wgrid, 128>>>(V1, comp1, loop1, V2, comp2, loop2);   // 2
    edge_mma_kernel<<<EGRID, 256, SMEM_EDGE>>>(pWh1, src, dst, norm,
                                               ph1, E);                   // 3
    relu_xh_kernel<<<xgrid, 256>>>(bias2, out, nN);                       // 4
    edge_mma_kernel<<<EGRID, 256, SMEM_EDGE>>>(pWh2, src, dst, norm,
                                               out, E);                   // 5
}

// round 15
// speedup vs baseline: 1.2302x; 1.2302x over previous
#include <cuda_runtime.h>
#include <cuda_fp16.h>
#include <cstdint>

#define H      128
#define NREL   237
#define NB     100
#define RTILE  16
#define MAXN   15000
#define MAXE   400000
#define EM     128        // edges per tile
#define CHUNK  256        // edges per CTA chunk (2 tiles, tile-aligned)
#define BPH    72         // smem pitch in uint32 (half2); 72%32==8 -> conflict-free LDS.64
#define SORTB  148        // sort blocks inside fused prep kernel
#define WBB    960        // wbuild blocks (2 k-pairs x 15 rgroups x 2 layers x 16... = 960)

// ---------------- device-global scratch (no runtime allocation) -------------
__device__ uint32_t g_Wh[2][(NREL + 1) * 8192]; // W^T fp16 per layer (slot NREL = loop_w)
__device__ uint32_t g_xh[MAXN * 64];          // x fp16, paired-k per row
__device__ float g_h1[MAXN * H];
__device__ int   g_perm[MAXE + MAXN];
__device__ int   g_counts[256];
__device__ int   g_start[256];
__device__ int   g_cursor[256];
__device__ int   g_cbase[257];                // chunk prefix per relation
__device__ unsigned g_barcnt;
__device__ unsigned g_barflag;

static const int SMEM_EDGE = 3 * 128 * BPH * 4 + 2 * 128 * 8;        // 112640

extern __shared__ char dyn_smem[];

// ---------------- PTX helpers ------------------------------------------------
__device__ __forceinline__ uint32_t h2pack(float a, float b) {
    __half2 h = __floats2half2_rn(a, b);   // a -> low, b -> high
    return *(uint32_t*)&h;
}
__device__ __forceinline__ void red_add_v4(float* p, float a, float b,
                                           float c, float d) {
    asm volatile("red.global.add.v4.f32 [%0], {%1,%2,%3,%4};"
                 :: "l"(p), "f"(a), "f"(b), "f"(c), "f"(d) : "memory");
}
__device__ __forceinline__ void mma_16n8k16(float* c, const uint32_t* a,
                                            uint32_t b0, uint32_t b1) {
    asm volatile(
        "mma.sync.aligned.m16n8k16.row.col.f32.f16.f16.f32 "
        "{%0,%1,%2,%3}, {%4,%5,%6,%7}, {%8,%9}, {%0,%1,%2,%3};"
        : "+f"(c[0]), "+f"(c[1]), "+f"(c[2]), "+f"(c[3])
        : "r"(a[0]), "r"(a[1]), "r"(a[2]), "r"(a[3]), "r"(b0), "r"(b1));
}
__device__ __forceinline__ void cpa16(void* s, const void* g) {
    uint32_t sa = (uint32_t)__cvta_generic_to_shared(s);
    asm volatile("cp.async.cg.shared.global [%0], [%1], 16;"
                 :: "r"(sa), "l"(g) : "memory");
}
__device__ __forceinline__ void cpa16z(void* s, const void* g) {
    uint32_t sa = (uint32_t)__cvta_generic_to_shared(s);
    asm volatile("cp.async.cg.shared.global [%0], [%1], 16, 0;"
                 :: "r"(sa), "l"(g) : "memory");
}
#define CPA_COMMIT() asm volatile("cp.async.commit_group;" ::: "memory")
#define CPA_WAIT1()  asm volatile("cp.async.wait_group 1;" ::: "memory")

// pack 16 consecutive floats (4 float4) into paired-k half2 order
__device__ __forceinline__ void pack_kgroup(const float4* u, uint4* o0, uint4* o1) {
    uint32_t q0 = h2pack(u[0].x, u[0].y), q1 = h2pack(u[0].z, u[0].w);
    uint32_t q2 = h2pack(u[1].x, u[1].y), q3 = h2pack(u[1].z, u[1].w);
    uint32_t q4 = h2pack(u[2].x, u[2].y), q5 = h2pack(u[2].z, u[2].w);
    uint32_t q6 = h2pack(u[3].x, u[3].y), q7 = h2pack(u[3].z, u[3].w);
    *o0 = make_uint4(q0, q4, q1, q5);
    *o1 = make_uint4(q2, q6, q3, q7);
}

// grid-wide barrier among the SORT blocks only (blocks 0..SORTB-1, resident
// in wave 1). Generation-based: state self-restores across graph replays.
__device__ __forceinline__ void gridbar(int nb) {
    __syncthreads();
    if (threadIdx.x == 0) {
        unsigned old = *(volatile unsigned*)&g_barflag;
        __threadfence();
        unsigned t = atomicAdd(&g_barcnt, 1);
        if (t == (unsigned)nb - 1) {
            g_barcnt = 0;
            __threadfence();
            atomicAdd(&g_barflag, 1);
        } else {
            while (*(volatile unsigned*)&g_barflag == old) {}
        }
        __threadfence();
    }
    __syncthreads();
}

// ================= fused prep kernel: sort | wbuild | gather ==================
// blocks [0,SORTB): relation counting-sort (grid-barrier within this range)
// blocks [SORTB, SORTB+WBB): W build, fp16 permuted output, both layers
// blocks [SORTB+WBB, ...): xh gather + bias init
__global__ void __launch_bounds__(256, 1)
prep_kernel(const int* __restrict__ etype, int E, int nN,
            const float* __restrict__ emb, const int* __restrict__ nids,
            const float* __restrict__ bias1, float* __restrict__ out1,
            const float* __restrict__ V1, const float* __restrict__ comp1,
            const float* __restrict__ loop1,
            const float* __restrict__ V2, const float* __restrict__ comp2,
            const float* __restrict__ loop2) {
    int bx = blockIdx.x, tid = threadIdx.x;

    if (bx < SORTB) {
        // ------------------- SORT role -------------------
        __shared__ int sh[256];
        __shared__ int ss[256];
        int b = bx, nb = SORTB;
        int total = E + nN;

        if (b == 0) g_counts[tid] = 0;
        gridbar(nb);

        sh[tid] = 0;
        __syncthreads();
        for (int e = b * 256 + tid; e < E; e += nb * 256)
            atomicAdd(&sh[etype[e]], 1);
        __syncthreads();
        if (sh[tid]) atomicAdd(&g_counts[tid], sh[tid]);
        gridbar(nb);

        if (b == 0) {
            int c = g_counts[tid] + ((tid == NREL) ? nN : 0);
            g_counts[tid] = c;
            ss[tid] = c;
            __syncthreads();
            #pragma unroll
            for (int off = 1; off < 256; off <<= 1) {
                int v = (tid >= off) ? ss[tid - off] : 0;
                __syncthreads();
                ss[tid] += v;
                __syncthreads();
            }
            g_start[tid] = ss[tid] - c;
            g_cursor[tid] = ss[tid] - c;
            __syncthreads();
            int C = (c + CHUNK - 1) / CHUNK;
            ss[tid] = C;
            __syncthreads();
            #pragma unroll
            for (int off = 1; off < 256; off <<= 1) {
                int v = (tid >= off) ? ss[tid - off] : 0;
                __syncthreads();
                ss[tid] += v;
                __syncthreads();
            }
            g_cbase[tid] = ss[tid] - C;
            if (tid == 255) g_cbase[256] = ss[255];
        }
        gridbar(nb);

        ss[tid] = (sh[tid] > 0) ? atomicAdd(&g_cursor[tid], sh[tid]) : 0;
        __syncthreads();
        for (int e = b * 256 + tid; e < E; e += nb * 256) {
            int p = atomicAdd(&ss[etype[e]], 1);
            g_perm[p] = e;
        }
        {
            int base = g_start[NREL];
            for (int i = b * 256 + tid; i < nN; i += nb * 256)
                g_perm[base + i] = E + i;
        }
        (void)total;
    } else if (bx < SORTB + WBB) {
        // ------------------- WBUILD role -------------------
        // w = [0,960): layer = w/480; rem = w%480; rgroup = rem/32; kpg = rem%32
        // thread handles kp = kpg*2 + (tid>>7), n = tid&127
        __shared__ float sC[RTILE * NB];
        int w = bx - SORTB;
        int layer = w / 480;
        int rem = w % 480;
        int r0 = (rem >> 5) * RTILE;
        int kp = ((rem & 31) << 1) + (tid >> 7);
        int n = tid & 127;
        const float* V     = layer ? V2 : V1;
        const float* comp  = layer ? comp2 : comp1;
        const float* loopw = layer ? loop2 : loop1;
        uint32_t* Wout = g_Wh[layer];

        for (int i = tid; i < RTILE * NB; i += 256) {
            int rr = i / NB, b = i % NB;
            int r = r0 + rr;
            sC[i] = (r < NREL) ? comp[r * NB + b] : 0.f;
        }
        __syncthreads();

        float a0[RTILE], a1[RTILE];
        #pragma unroll
        for (int rr = 0; rr < RTILE; rr++) { a0[rr] = 0.f; a1[rr] = 0.f; }
        const float* v0p = V + (size_t)(2 * kp) * 128 + n;
        #pragma unroll 2
        for (int b = 0; b < NB; b++) {
            float v0 = v0p[(size_t)b * (H * H)];
            float v1 = v0p[(size_t)b * (H * H) + 128];
            #pragma unroll
            for (int rr = 0; rr < RTILE; rr++) {
                float c = sC[rr * NB + b];
                a0[rr] += c * v0;
                a1[rr] += c * v1;
            }
        }
        int half = n >> 6, remn = n & 63;
        int qq = remn >> 4, t4 = (remn >> 2) & 3, p = (remn >> 1) & 1, bb = remn & 1;
        int srow = half * 64 + (2 * qq + p) * 8 + t4 * 2 + bb;
        int kg = kp >> 3, j0 = kp & 7;
        int pos = (j0 < 4) ? 2 * j0 : 2 * j0 - 7;
        int off = srow * 64 + kg * 8 + pos;
        #pragma unroll
        for (int rr = 0; rr < RTILE; rr++) {
            int r = r0 + rr;
            if (r < NREL) {
                Wout[(size_t)r * 8192 + off] = h2pack(a0[rr], a1[rr]);
            } else if (r == NREL) {
                float l0 = loopw[(size_t)(2 * kp) * 128 + n];
                float l1 = loopw[(size_t)(2 * kp + 1) * 128 + n];
                Wout[(size_t)NREL * 8192 + off] = h2pack(l0, l1);
            }
        }
    } else {
        // ------------------- GATHER role -------------------
        int idx = (bx - SORTB - WBB) * 256 + tid;
        if (idx >= nN * 8) return;
        int node = idx >> 3, kg = idx & 7;
        const float4* xr = (const float4*)emb + (size_t)nids[node] * 32 + kg * 4;
        float4 u[4] = {xr[0], xr[1], xr[2], xr[3]};
        uint4 o0, o1;
        pack_kgroup(u, &o0, &o1);
        uint4* d = (uint4*)(g_xh + (size_t)node * 64 + kg * 8);
        d[0] = o0; d[1] = o1;
        const float4* b4 = (const float4*)bias1 + kg * 4;
        float4* ob = (float4*)out1 + (size_t)node * 32 + kg * 4;
        #pragma unroll
        for (int i = 0; i < 4; i++) ob[i] = b4[i];
    }
}

// ---- relu h1 -> g_xh (fp16 paired-k); out init = bias2 ---------------------
__global__ void relu_xh_kernel(const float* __restrict__ bias,
                               float* __restrict__ outinit, int n) {
    int idx = blockIdx.x * blockDim.x + threadIdx.x;
    if (idx >= n * 8) return;
    int node = idx >> 3, kg = idx & 7;
    const float4* hr = (const float4*)g_h1 + (size_t)node * 32 + kg * 4;
    float4 u[4];
    #pragma unroll
    for (int i = 0; i < 4; i++) {
        float4 v = hr[i];
        v.x = fmaxf(v.x, 0.f); v.y = fmaxf(v.y, 0.f);
        v.z = fmaxf(v.z, 0.f); v.w = fmaxf(v.w, 0.f);
        u[i] = v;
    }
    uint4 o0, o1;
    pack_kgroup(u, &o0, &o1);
    uint4* d = (uint4*)(g_xh + (size_t)node * 64 + kg * 8);
    d[0] = o0; d[1] = o1;
    const float4* b4 = (const float4*)bias + kg * 4;
    float4* ob = (float4*)outinit + (size_t)node * 32 + kg * 4;
    #pragma unroll
    for (int i = 0; i < 4; i++) ob[i] = b4[i];
}

// ---------------- FP16 mma.sync edge GEMM, chunked + double-buffered ---------
// Each CTA handles one tile-aligned chunk (<= 2 tiles) of one relation.
__global__ void __launch_bounds__(256, 1)
edge_mma_kernel(const uint32_t* __restrict__ Wh,
                const int* __restrict__ src,
                const int* __restrict__ dst,
                const float* __restrict__ norm,
                float* __restrict__ hout, int E) {
    uint32_t* sB  = (uint32_t*)dyn_smem;          // [128][BPH]
    uint32_t* sA0 = sB + 128 * BPH;               // [128][BPH] buf 0
    uint32_t* sA1 = sA0 + 128 * BPH;              // [128][BPH] buf 1
    int*   sDst = (int*)(sA1 + 128 * BPH);        // [2][128]
    float* sNrm = (float*)(sDst + 256);           // [2][128]

    int tid = threadIdx.x, lane = tid & 31, wid = tid >> 5;
    int g = lane >> 2, tig = lane & 3;
    int wm = wid >> 1, wn = wid & 1;              // 4 x 2 warp grid
    int m0 = wm * 32, n0 = wn * 64;

    // ---- chunk lookup: binary search in cached prefix ----
    int* sCb = sDst;                              // reuse staging smem
    for (int i = tid; i < NREL + 2; i += 256) sCb[i] = g_cbase[i];
    __syncthreads();
    int bx = blockIdx.x;
    if (bx >= sCb[NREL + 1]) return;
    int loI = 0, hiI = NREL;
    while (loI < hiI) {
        int mid = (loI + hiI + 1) >> 1;
        if (sCb[mid] <= bx) loI = mid; else hiI = mid - 1;
    }
    int rel = loI;
    int lo = g_start[rel] + (bx - sCb[rel]) * CHUNK;
    int hi = min(g_start[rel] + g_counts[rel], lo + CHUNK);
    __syncthreads();                              // done reading sCb

    // ---- B: cp.async copy of pre-permuted fp16 W tile (32KB) ----
    {
        const uint32_t* wb = Wh + (size_t)rel * 8192;
        #pragma unroll
        for (int i = 0; i < 8; i++) {
            int c = tid + i * 256;
            int row = c >> 4, cc = c & 15;
            cpa16(&sB[row * BPH + cc * 4], &wb[row * 64 + cc * 4]);
        }
    }

    int arow = tid >> 1, ahalf = tid & 1;

    auto issueA = [&](int t0, uint32_t* sAb, int bsel) {
        int r = t0 + arow;
        uint32_t* sp = sAb + arow * BPH + ahalf * 32;
        if (r < hi) {
            int e = g_perm[r];
            int node;
            if (e < E) {
                node = src[e];
                if (ahalf == 0) {
                    sDst[bsel * 128 + arow] = dst[e];
                    sNrm[bsel * 128 + arow] = norm[e];
                }
            } else {
                node = e - E;    // self-loop pseudo-edge
                if (ahalf == 0) {
                    sDst[bsel * 128 + arow] = node;
                    sNrm[bsel * 128 + arow] = 1.0f;
                }
            }
            const uint32_t* gp = g_xh + (size_t)node * 64 + ahalf * 32;
            #pragma unroll
            for (int c = 0; c < 8; c++) cpa16(sp + c * 4, gp + c * 4);
        } else {
            #pragma unroll
            for (int c = 0; c < 8; c++) cpa16z(sp + c * 4, g_xh);
        }
    };

    int ntiles = (hi - lo + EM - 1) / EM;
    issueA(lo, sA0, 0);
    CPA_COMMIT();                                  // group0 = B + A(0)

    for (int it = 0; it < ntiles; it++) {
        int t0 = lo + it * EM;
        if (it + 1 < ntiles)
            issueA(t0 + EM, ((it + 1) & 1) ? sA1 : sA0, (it + 1) & 1);
        CPA_COMMIT();
        CPA_WAIT1();
        __syncthreads();

        uint32_t* sA = (it & 1) ? sA1 : sA0;
        int bsel = it & 1;
        int tsize = min(EM, hi - t0);

        float acc[2][8][4];
        #pragma unroll
        for (int mi = 0; mi < 2; mi++)
            #pragma unroll
            for (int ni = 0; ni < 8; ni++)
                #pragma unroll
                for (int c = 0; c < 4; c++) acc[mi][ni][c] = 0.f;

        #pragma unroll
        for (int ks = 0; ks < 8; ks++) {
            int base = ks * 8 + 2 * tig;
            uint32_t a[2][4];
            #pragma unroll
            for (int mi = 0; mi < 2; mi++) {
                uint2 alo = *(const uint2*)&sA[(m0 + mi * 16 + g) * BPH + base];
                uint2 ahi = *(const uint2*)&sA[(m0 + mi * 16 + g + 8) * BPH + base];
                a[mi][0] = alo.x; a[mi][2] = alo.y;
                a[mi][1] = ahi.x; a[mi][3] = ahi.y;
            }
            #pragma unroll
            for (int ni = 0; ni < 8; ni++) {
                uint2 bb = *(const uint2*)&sB[(n0 + ni * 8 + g) * BPH + base];
                mma_16n8k16(acc[0][ni], a[0], bb.x, bb.y);
                mma_16n8k16(acc[1][ni], a[1], bb.x, bb.y);
            }
        }

        #pragma unroll
        for (int mi = 0; mi < 2; mi++) {
            int r0 = m0 + mi * 16 + g;
            int r1 = r0 + 8;
            bool v0 = r0 < tsize, v1 = r1 < tsize;
            float nr0 = sNrm[bsel * 128 + r0], nr1 = sNrm[bsel * 128 + r1];
            float* p0 = hout + (size_t)sDst[bsel * 128 + r0] * H;
            float* p1 = hout + (size_t)sDst[bsel * 128 + r1] * H;
            #pragma unroll
            for (int q = 0; q < 4; q++) {
                int c = n0 + q * 16 + tig * 4;
                if (v0) red_add_v4(p0 + c,
                                   acc[mi][2 * q][0] * nr0,
                                   acc[mi][2 * q][1] * nr0,
                                   acc[mi][2 * q + 1][0] * nr0,
                                   acc[mi][2 * q + 1][1] * nr0);
                if (v1) red_add_v4(p1 + c,
                                   acc[mi][2 * q][2] * nr1,
                                   acc[mi][2 * q][3] * nr1,
                                   acc[mi][2 * q + 1][2] * nr1,
                                   acc[mi][2 * q + 1][3] * nr1);
            }
        }
        __syncthreads();
    }
}

// ---------------- host orchestration ----------------------------------------
extern "C" void kernel_launch(void* const* d_in, const int* in_sizes, int n_in,
                              void* d_out, int out_size) {
    const int*   nids  = (const int*)d_in[0];
    const int*   src   = (const int*)d_in[1];
    const int*   dst   = (const int*)d_in[2];
    const int*   etype = (const int*)d_in[3];
    const float* norm  = (const float*)d_in[4];
    const float* emb   = (const float*)d_in[6];
    const float* V1    = (const float*)d_in[7];
    const float* comp1 = (const float*)d_in[8];
    const float* loop1 = (const float*)d_in[9];
    const float* bias1 = (const float*)d_in[10];
    const float* V2    = (const float*)d_in[11];
    const float* comp2 = (const float*)d_in[12];
    const float* loop2 = (const float*)d_in[13];
    const float* bias2 = (const float*)d_in[14];
    float* out = (float*)d_out;

    int nN = in_sizes[0];
    int E  = in_sizes[1];

    cudaFuncSetAttribute(edge_mma_kernel,
                         cudaFuncAttributeMaxDynamicSharedMemorySize, SMEM_EDGE);

    float* ph1 = nullptr;
    uint32_t* pWh = nullptr;
    cudaGetSymbolAddress((void**)&ph1, g_h1);
    cudaGetSymbolAddress((void**)&pWh, g_Wh);
    uint32_t* pWh1 = pWh;
    uint32_t* pWh2 = pWh + (size_t)(NREL + 1) * 8192;

    int gb = (nN * 8 + 255) / 256;                 // gather blocks
    int pgrid = SORTB + WBB + gb;
    int egrid = (E + nN + CHUNK - 1) / CHUNK + NREL + 1;  // upper bound
    int xgrid = gb;

    prep_kernel<<<pgrid, 256>>>(etype, E, nN, emb, nids, bias1, ph1,
                                V1, comp1, loop1, V2, comp2, loop2);      // 0
    edge_mma_kernel<<<egrid, 256, SMEM_EDGE>>>(pWh1, src, dst, norm,
                                               ph1, E);                   // 1
    relu_xh_kernel<<<xgrid, 256>>>(bias2, out, nN);                       // 2
    edge_mma_kernel<<<egrid, 256, SMEM_EDGE>>>(pWh2, src, dst, norm,
                                               out, E);                   // 3
}